// round 4
// baseline (speedup 1.0000x reference)
#include <cuda_runtime.h>
#include <math.h>
#include <cstdint>

#define B_SZ   512
#define I_CAPS 1152
#define Q_SZ   8
#define O_CAPS 10
#define P_SZ   16
#define K_TOT  9216          // I*Q
#define N_TOT  160           // O*P
#define NT_N   20            // N_TOT/8
#define KB_S   1152          // K_TOT/8   (k-blocks of 8 for s-GEMM)
#define KB_G   64            // B_SZ/8    (b-blocks of 8 for G-GEMM)
#define MT_S   32            // B_SZ/16   (m-tiles for s)
#define MT_G   576           // K_TOT/16  (m-tiles for G)
#define KSPLIT_S 72          // chunk = 16 k-blocks = 128 k
#define BSPLIT_G 4           // chunk = 16 b-blocks = 128 b

typedef unsigned u32;

// ---------------- static device scratch ----------------
__device__ float g_Wt[K_TOT * N_TOT];                  // [k][n] fp32 for b_update
__device__ float g_b[I_CAPS * O_CAPS];
__device__ float g_c[I_CAPS * O_CAPS];
__device__ float g_spart[KSPLIT_S][B_SZ * N_TOT];
__device__ float g_v[B_SZ * N_TOT];
__device__ float g_Gpart[BSPLIT_G][K_TOT * N_TOT];
// fragment-ready operands: uint4 = {hi0, lo0, hi1, lo1} (tf32 bit patterns)
__device__ uint4 g_afrag_s[MT_S * KB_S * 2 * 32];      // A for s  (x),  37.7 MB
__device__ uint4 g_afrag_g[MT_G * KB_G * 2 * 32];      // A for G  (xT), 37.7 MB
__device__ uint4 g_bfrag  [NT_N * KB_S * 32];          // B for s  (c.W), 11.8 MB
__device__ uint4 g_vfrag  [NT_N * KB_G * 32];          // B for G  (vT)

// ---------------- helpers ----------------
__device__ __forceinline__ u32 tf32_hi(float v) {
    u32 r; asm("cvt.rna.tf32.f32 %0, %1;" : "=r"(r) : "f"(v)); return r;
}
__device__ __forceinline__ uint4 split2(float v0, float v1) {
    u32 h0 = tf32_hi(v0);
    u32 l0 = tf32_hi(v0 - __uint_as_float(h0));
    u32 h1 = tf32_hi(v1);
    u32 l1 = tf32_hi(v1 - __uint_as_float(h1));
    return make_uint4(h0, l0, h1, l1);
}
__device__ __forceinline__ void mma_tf32(float* d, u32 a0, u32 a1, u32 a2, u32 a3,
                                         u32 b0, u32 b1) {
    asm volatile(
        "mma.sync.aligned.m16n8k8.row.col.f32.tf32.tf32.f32 "
        "{%0,%1,%2,%3}, {%4,%5,%6,%7}, {%8,%9}, {%0,%1,%2,%3};"
        : "+f"(d[0]), "+f"(d[1]), "+f"(d[2]), "+f"(d[3])
        : "r"(a0), "r"(a1), "r"(a2), "r"(a3), "r"(b0), "r"(b1));
}

// ---------------- prep: Wt fp32 [k][n]; zero b ----------------
__global__ void wt_kernel(const float* __restrict__ W) {
    int t = blockIdx.x * 256 + threadIdx.x;
    if (t < I_CAPS * O_CAPS) g_b[t] = 0.0f;
    if (t >= K_TOT * N_TOT) return;
    int k = t / N_TOT, n = t - k * N_TOT;
    int i = k >> 3, q = k & 7, o = n >> 4, p = n & 15;
    g_Wt[t] = W[(i * O_CAPS + o) * (P_SZ * Q_SZ) + p * Q_SZ + q];
}

// ---------------- one-time: x -> A-fragments for s and G ----------------
// grid (K_TOT/128, B_SZ/16), 256 threads. Stage a 16(batch) x 128(k) tile.
__global__ void xprep_kernel(const float* __restrict__ x) {
    __shared__ float st[16][129];
    const int bx = blockIdx.x, by = blockIdx.y;
    const int k0 = bx * 128, b0 = by * 16;
    const int t = threadIdx.x, wid = t >> 5, l = t & 31;
    const int gid = l >> 2, tid = l & 3;

    // coalesced load: 512 float4
    #pragma unroll
    for (int j = 0; j < 2; j++) {
        int f = t + 256 * j;              // 0..511
        int row = f >> 5, c4 = f & 31;
        float4 v = *(const float4*)&x[(size_t)(b0 + row) * K_TOT + k0 + c4 * 4];
        st[row][c4 * 4 + 0] = v.x; st[row][c4 * 4 + 1] = v.y;
        st[row][c4 * 4 + 2] = v.z; st[row][c4 * 4 + 3] = v.w;
    }
    __syncthreads();

    for (int task = wid; task < 64; task += 8) {
        if (task < 32) {
            // s-frag: m = batch, contraction = k. mt16 = by, kb = bx*16 + kbl
            int kbl = task >> 1, h = task & 1;
            int col = kbl * 8 + tid + h * 4;
            float v0 = st[gid][col];
            float v1 = st[gid + 8][col];
            g_afrag_s[(((size_t)by * KB_S + bx * 16 + kbl) * 2 + h) * 32 + l] = split2(v0, v1);
        } else {
            // G-frag: m = k, contraction = b. mt16 = bx*8+kt, bb = by*2+bbl
            int id = task - 32;
            int kt = id >> 2, bbl = (id >> 1) & 1, h = id & 1;
            int brow = bbl * 8 + tid + h * 4;
            int kcol = kt * 16 + gid;
            float v0 = st[brow][kcol];
            float v1 = st[brow][kcol + 8];
            g_afrag_g[(((size_t)(bx * 8 + kt) * KB_G + by * 2 + bbl) * 2 + h) * 32 + l] = split2(v0, v1);
        }
    }
}

// ---------------- softmax over i (one warp per o) ----------------
__global__ void softmax_kernel() {
    int o = threadIdx.x >> 5, lane = threadIdx.x & 31;
    float mx = -1e30f;
    for (int i = lane; i < I_CAPS; i += 32) mx = fmaxf(mx, g_b[i * O_CAPS + o]);
    #pragma unroll
    for (int off = 16; off; off >>= 1) mx = fmaxf(mx, __shfl_xor_sync(~0u, mx, off));
    float sum = 0.0f;
    for (int i = lane; i < I_CAPS; i += 32) sum += expf(g_b[i * O_CAPS + o] - mx);
    #pragma unroll
    for (int off = 16; off; off >>= 1) sum += __shfl_xor_sync(~0u, sum, off);
    float inv = 1.0f / sum;
    for (int i = lane; i < I_CAPS; i += 32)
        g_c[i * O_CAPS + o] = expf(g_b[i * O_CAPS + o] - mx) * inv;
}

// ---------------- per-iter: B-fragments of (c .* W), one warp per (nt, kb) ----------------
__global__ void bfrag_kernel(const float* __restrict__ W) {
    int wg = blockIdx.x * 8 + (threadIdx.x >> 5);    // < 20*1152
    int l = threadIdx.x & 31;
    int nt = wg / KB_S, kb = wg - nt * KB_S;         // i = kb
    int gid = l >> 2, tid = l & 3;
    int n = nt * 8 + gid;
    int o = n >> 4, p = n & 15;
    float cs = g_c[kb * O_CAPS + o];
    const float* wrow = &W[((kb * O_CAPS + o) * P_SZ + p) * Q_SZ];
    float v0 = cs * wrow[tid];
    float v1 = cs * wrow[tid + 4];
    g_bfrag[((size_t)nt * KB_S + kb) * 32 + l] = split2(v0, v1);
}

// ---------------- per-iter: B-fragments of vT, one warp per (nt, bb) ----------------
__global__ void vfrag_kernel() {
    int wg = blockIdx.x * 8 + (threadIdx.x >> 5);    // < 20*64
    int l = threadIdx.x & 31;
    int nt = wg / KB_G, bb = wg - nt * KB_G;
    int gid = l >> 2, tid = l & 3;
    int n = nt * 8 + gid;
    float v0 = g_v[(bb * 8 + tid) * N_TOT + n];
    float v1 = g_v[(bb * 8 + tid + 4) * N_TOT + n];
    g_vfrag[((size_t)nt * KB_G + bb) * 32 + l] = split2(v0, v1);
}

// ---------------- unified split-tf32 tensor GEMM ----------------
// mode 0: s-GEMM  grid (4, KSPLIT_S)   out g_spart[by]
// mode 1: G-GEMM  grid (72, BSPLIT_G)  out g_Gpart[by]
// CTA: 4 warps, each 32m x 160n; chunk = 16 contraction blocks of 8.
__global__ void __launch_bounds__(128) mma_gemm_kernel(int mode) {
    const int t = threadIdx.x, w = t >> 5, l = t & 31;
    const int gid = l >> 2, tid = l & 3;

    const uint4 *A, *B;
    int AKB, mtbase;
    float* out;
    if (mode == 0) {
        A = g_afrag_s; B = g_bfrag; AKB = KB_S;
        mtbase = blockIdx.x * 8 + w * 2;
        out = &g_spart[blockIdx.y][0];
    } else {
        A = g_afrag_g; B = g_vfrag; AKB = KB_G;
        mtbase = blockIdx.x * 8 + w * 2;
        out = &g_Gpart[blockIdx.y][0];
    }
    const int kb0 = blockIdx.y * 16;

    float d[2][NT_N][4];
    #pragma unroll
    for (int a = 0; a < 2; a++)
        #pragma unroll
        for (int nt = 0; nt < NT_N; nt++)
            #pragma unroll
            for (int e = 0; e < 4; e++) d[a][nt][e] = 0.0f;

    #pragma unroll 1
    for (int kb = 0; kb < 16; ++kb) {
        uint4 a00 = A[(((size_t)(mtbase + 0) * AKB + kb0 + kb) * 2 + 0) * 32 + l];
        uint4 a01 = A[(((size_t)(mtbase + 0) * AKB + kb0 + kb) * 2 + 1) * 32 + l];
        uint4 a10 = A[(((size_t)(mtbase + 1) * AKB + kb0 + kb) * 2 + 0) * 32 + l];
        uint4 a11 = A[(((size_t)(mtbase + 1) * AKB + kb0 + kb) * 2 + 1) * 32 + l];
        const uint4* Bk = &B[(size_t)(kb0 + kb) * 32 + l];
        #pragma unroll
        for (int nt = 0; nt < NT_N; nt++) {
            uint4 b = Bk[(size_t)nt * AKB * 32];
            // tile 0: D += Ah*Bh + Ah*Bl + Al*Bh
            mma_tf32(d[0][nt], a00.x, a00.z, a01.x, a01.z, b.x, b.z);
            mma_tf32(d[0][nt], a00.x, a00.z, a01.x, a01.z, b.y, b.w);
            mma_tf32(d[0][nt], a00.y, a00.w, a01.y, a01.w, b.x, b.z);
            // tile 1
            mma_tf32(d[1][nt], a10.x, a10.z, a11.x, a11.z, b.x, b.z);
            mma_tf32(d[1][nt], a10.x, a10.z, a11.x, a11.z, b.y, b.w);
            mma_tf32(d[1][nt], a10.y, a10.w, a11.y, a11.w, b.x, b.z);
        }
    }

    // epilogue
    #pragma unroll
    for (int a = 0; a < 2; a++) {
        int m = (mtbase + a) * 16 + gid;
        #pragma unroll
        for (int nt = 0; nt < NT_N; nt++) {
            int col = nt * 8 + tid * 2;
            *(float2*)&out[(size_t)m * N_TOT + col] = make_float2(d[a][nt][0], d[a][nt][1]);
            *(float2*)&out[(size_t)(m + 8) * N_TOT + col] = make_float2(d[a][nt][2], d[a][nt][3]);
        }
    }
}

// ---------------- reduce split-K + squash ----------------
__global__ void squash_kernel(float* __restrict__ out, int write_out) {
    int tid = blockIdx.x * 256 + threadIdx.x;   // < 81920
    float sv = 0.0f;
    #pragma unroll 8
    for (int sp = 0; sp < KSPLIT_S; ++sp) sv += g_spart[sp][tid];
    float sq = sv * sv;
    #pragma unroll
    for (int off = 8; off; off >>= 1) sq += __shfl_xor_sync(~0u, sq, off);
    float norm = sqrtf(sq + 1e-8f);
    float vv = (sq / (1.0f + sq)) * (sv / norm);
    g_v[tid] = vv;
    if (write_out) out[tid] = vv;
}

// ---------------- b[i,o] += (1/512) * sum over 8x16 block of Wt .* (sum Gpart) ----------------
__global__ void b_update_kernel() {
    int w = (blockIdx.x * 256 + threadIdx.x) >> 5;
    int lane = threadIdx.x & 31;
    if (w >= I_CAPS * O_CAPS) return;
    int i = w / O_CAPS, o = w - i * O_CAPS;
    int row = i * 8 + (lane >> 2);
    int col = o * 16 + (lane & 3) * 4;
    int base = row * N_TOT + col;
    float4 wv = *(const float4*)&g_Wt[base];
    float4 g0 = *(const float4*)&g_Gpart[0][base];
    float4 g1 = *(const float4*)&g_Gpart[1][base];
    float4 g2 = *(const float4*)&g_Gpart[2][base];
    float4 g3 = *(const float4*)&g_Gpart[3][base];
    float dd = wv.x * (g0.x + g1.x + g2.x + g3.x)
             + wv.y * (g0.y + g1.y + g2.y + g3.y)
             + wv.z * (g0.z + g1.z + g2.z + g3.z)
             + wv.w * (g0.w + g1.w + g2.w + g3.w);
    #pragma unroll
    for (int off = 16; off; off >>= 1) dd += __shfl_xor_sync(~0u, dd, off);
    if (lane == 0) g_b[w] += dd * (1.0f / (float)B_SZ);
}

// ---------------- launch ----------------
extern "C" void kernel_launch(void* const* d_in, const int* in_sizes, int n_in,
                              void* d_out, int out_size) {
    const float* x = (const float*)d_in[0];
    const float* W = (const float*)d_in[1];
    if (n_in >= 2 && in_sizes[0] == I_CAPS * O_CAPS * P_SZ * Q_SZ) {
        W = (const float*)d_in[0];
        x = (const float*)d_in[1];
    }
    float* out = (float*)d_out;

    wt_kernel<<<(K_TOT * N_TOT + 255) / 256, 256>>>(W);
    xprep_kernel<<<dim3(K_TOT / 128, B_SZ / 16), 256>>>(x);

    for (int it = 0; it < 3; ++it) {
        softmax_kernel<<<1, 32 * O_CAPS>>>();
        bfrag_kernel<<<(NT_N * KB_S) / 8, 256>>>(W);
        mma_gemm_kernel<<<dim3(MT_S / 8, KSPLIT_S), 128>>>(0);
        squash_kernel<<<(B_SZ * N_TOT) / 256, 256>>>(out, it == 2 ? 1 : 0);
        if (it < 2) {
            vfrag_kernel<<<(NT_N * KB_G) / 8, 256>>>();
            mma_gemm_kernel<<<dim3(MT_G / 8, BSPLIT_G), 128>>>(1);
            b_update_kernel<<<(I_CAPS * O_CAPS * 32 + 255) / 256, 256>>>();
        }
    }
}

// round 5
// speedup vs baseline: 1.6986x; 1.6986x over previous
#include <cuda_runtime.h>
#include <cuda_bf16.h>
#include <math.h>
#include <cstdint>

#define B_SZ   512
#define I_CAPS 1152
#define Q_SZ   8
#define O_CAPS 10
#define P_SZ   16
#define K_TOT  9216          // I*Q
#define N_TOT  160           // O*P
#define NT_N   20            // N_TOT/8
#define KB16_S 576           // K_TOT/16  (k-blocks of 16 for s-GEMM)
#define KB16_G 32            // B_SZ/16   (b-blocks of 16 for G-GEMM)
#define MT_S   32            // B_SZ/16
#define MT_G   576           // K_TOT/16
#define KSPLIT_S 72          // 8 kb16 per split (128 k)
#define BSPLIT_G 4           // 8 bb16 per split (128 b)

typedef unsigned u32;

// ---------------- static device scratch ----------------
__device__ float g_Wt[K_TOT * N_TOT];                  // [k][n] fp32 for b_update
__device__ float g_b[I_CAPS * O_CAPS];
__device__ float g_c[I_CAPS * O_CAPS];
__device__ float g_spart[KSPLIT_S][B_SZ * N_TOT];
__device__ float g_v[B_SZ * N_TOT];
__device__ float g_Gpart[BSPLIT_G][K_TOT * N_TOT];
// A fragments: per (mt,kb): hi uint4 then lo uint4, 32 lanes each
__device__ uint4 g_afs[MT_S * KB16_S * 2 * 32];        // x   18.9 MB
__device__ uint4 g_afg[MT_G * KB16_G * 2 * 32];        // xT  18.9 MB
// B fragments: kb-major: index (kb*20 + nt)*32 + lane; uint4 = {bh0,bh1,bl0,bl1}
__device__ uint4 g_bf[KB16_S * NT_N * 32];             // c.W  5.9 MB
__device__ uint4 g_vf[KB16_G * NT_N * 32];             // vT

// ---------------- helpers ----------------
__device__ __forceinline__ void split_pair(float v0, float v1, u32 &hi, u32 &lo) {
    __nv_bfloat16 h0 = __float2bfloat16(v0), h1 = __float2bfloat16(v1);
    __nv_bfloat16 l0 = __float2bfloat16(v0 - __bfloat162float(h0));
    __nv_bfloat16 l1 = __float2bfloat16(v1 - __bfloat162float(h1));
    hi = (u32)__bfloat16_as_ushort(h0) | ((u32)__bfloat16_as_ushort(h1) << 16);
    lo = (u32)__bfloat16_as_ushort(l0) | ((u32)__bfloat16_as_ushort(l1) << 16);
}
__device__ __forceinline__ void mma_bf16(float* d, u32 a0, u32 a1, u32 a2, u32 a3,
                                         u32 b0, u32 b1) {
    asm volatile(
        "mma.sync.aligned.m16n8k16.row.col.f32.bf16.bf16.f32 "
        "{%0,%1,%2,%3}, {%4,%5,%6,%7}, {%8,%9}, {%0,%1,%2,%3};"
        : "+f"(d[0]), "+f"(d[1]), "+f"(d[2]), "+f"(d[3])
        : "r"(a0), "r"(a1), "r"(a2), "r"(a3), "r"(b0), "r"(b1));
}

// ---------------- prep: Wt fp32 [k][n]; zero b ----------------
__global__ void wt_kernel(const float* __restrict__ W) {
    int t = blockIdx.x * 256 + threadIdx.x;
    if (t < I_CAPS * O_CAPS) g_b[t] = 0.0f;
    if (t >= K_TOT * N_TOT) return;
    int k = t / N_TOT, n = t - k * N_TOT;
    int i = k >> 3, q = k & 7, o = n >> 4, p = n & 15;
    g_Wt[t] = W[(i * O_CAPS + o) * (P_SZ * Q_SZ) + p * Q_SZ + q];
}

// ---------------- one-time: x -> A fragments (s and G) ----------------
// grid (K_TOT/128 = 72, B_SZ/16 = 32), 256 threads. Tile: 16 batch x 128 k.
__global__ void xprep_kernel(const float* __restrict__ x) {
    __shared__ float st[16][129];
    const int bx = blockIdx.x, by = blockIdx.y;
    const int k0 = bx * 128, b0 = by * 16;
    const int t = threadIdx.x, w = t >> 5, l = t & 31;
    const int gid = l >> 2, tid = l & 3;

    #pragma unroll
    for (int j = 0; j < 2; j++) {
        int f = t + 256 * j;                  // 0..511
        int row = f >> 5, c4 = f & 31;
        float4 v = *(const float4*)&x[(size_t)(b0 + row) * K_TOT + k0 + c4 * 4];
        st[row][c4 * 4 + 0] = v.x; st[row][c4 * 4 + 1] = v.y;
        st[row][c4 * 4 + 2] = v.z; st[row][c4 * 4 + 3] = v.w;
    }
    __syncthreads();

    // warp w handles kb-sub-block j = w (16 k columns at j*16)
    const int j16 = w * 16;
    // --- s fragment: (mt = by, kb = bx*8 + w); m=batch rows, k=contraction ---
    {
        uint4 hi, lo;
        split_pair(st[gid][j16 + 2 * tid],     st[gid][j16 + 2 * tid + 1],     hi.x, lo.x);
        split_pair(st[gid + 8][j16 + 2 * tid], st[gid + 8][j16 + 2 * tid + 1], hi.y, lo.y);
        split_pair(st[gid][j16 + 2 * tid + 8], st[gid][j16 + 2 * tid + 9],     hi.z, lo.z);
        split_pair(st[gid + 8][j16 + 2 * tid + 8], st[gid + 8][j16 + 2 * tid + 9], hi.w, lo.w);
        size_t base = (((size_t)by * KB16_S + bx * 8 + w) * 2) * 32 + l;
        g_afs[base] = hi;
        g_afs[base + 32] = lo;
    }
    // --- G fragment: (mt = bx*8 + w, bb = by); m=k rows, b=contraction ---
    {
        uint4 hi, lo;
        split_pair(st[2 * tid][j16 + gid],         st[2 * tid + 1][j16 + gid],     hi.x, lo.x);
        split_pair(st[2 * tid][j16 + gid + 8],     st[2 * tid + 1][j16 + gid + 8], hi.y, lo.y);
        split_pair(st[2 * tid + 8][j16 + gid],     st[2 * tid + 9][j16 + gid],     hi.z, lo.z);
        split_pair(st[2 * tid + 8][j16 + gid + 8], st[2 * tid + 9][j16 + gid + 8], hi.w, lo.w);
        size_t base = (((size_t)(bx * 8 + w) * KB16_G + by) * 2) * 32 + l;
        g_afg[base] = hi;
        g_afg[base + 32] = lo;
    }
}

// ---------------- softmax over i (one warp per o) ----------------
__global__ void softmax_kernel() {
    int o = threadIdx.x >> 5, lane = threadIdx.x & 31;
    float mx = -1e30f;
    for (int i = lane; i < I_CAPS; i += 32) mx = fmaxf(mx, g_b[i * O_CAPS + o]);
    #pragma unroll
    for (int off = 16; off; off >>= 1) mx = fmaxf(mx, __shfl_xor_sync(~0u, mx, off));
    float sum = 0.0f;
    for (int i = lane; i < I_CAPS; i += 32) sum += expf(g_b[i * O_CAPS + o] - mx);
    #pragma unroll
    for (int off = 16; off; off >>= 1) sum += __shfl_xor_sync(~0u, sum, off);
    float inv = 1.0f / sum;
    for (int i = lane; i < I_CAPS; i += 32)
        g_c[i * O_CAPS + o] = expf(g_b[i * O_CAPS + o] - mx) * inv;
}

// ---------------- per-iter: B fragments of (c .* W), one warp per (kb, nt) ----------------
__global__ void bfrag_kernel(const float* __restrict__ W) {
    int wg = blockIdx.x * 8 + (threadIdx.x >> 5);     // kb*20 + nt, < 11520
    int l = threadIdx.x & 31;
    int kb = wg / NT_N, nt = wg - kb * NT_N;
    int gid = l >> 2, tid = l & 3;
    int n = nt * 8 + gid, o = n >> 4, p = n & 15;
    int i0 = kb * 2, i1 = kb * 2 + 1;
    float c0 = g_c[i0 * O_CAPS + o], c1 = g_c[i1 * O_CAPS + o];
    const float* w0 = &W[((i0 * O_CAPS + o) * P_SZ + p) * Q_SZ];
    const float* w1 = &W[((i1 * O_CAPS + o) * P_SZ + p) * Q_SZ];
    uint4 r;
    split_pair(c0 * w0[2 * tid], c0 * w0[2 * tid + 1], r.x, r.z);   // b0 (k=2tid..)
    split_pair(c1 * w1[2 * tid], c1 * w1[2 * tid + 1], r.y, r.w);   // b1 (k=2tid+8..)
    g_bf[(size_t)wg * 32 + l] = r;
}

// ---------------- per-iter: B fragments of vT, one warp per (bb, nt) ----------------
__global__ void vfrag_kernel() {
    int wg = blockIdx.x * 8 + (threadIdx.x >> 5);     // bb*20 + nt, < 640
    int l = threadIdx.x & 31;
    int bb = wg / NT_N, nt = wg - bb * NT_N;
    int gid = l >> 2, tid = l & 3;
    int n = nt * 8 + gid;
    int b0 = bb * 16 + 2 * tid;
    uint4 r;
    split_pair(g_v[b0 * N_TOT + n],       g_v[(b0 + 1) * N_TOT + n], r.x, r.z);
    split_pair(g_v[(b0 + 8) * N_TOT + n], g_v[(b0 + 9) * N_TOT + n], r.y, r.w);
    g_vf[(size_t)wg * 32 + l] = r;
}

// ---------------- unified split-bf16 tensor GEMM ----------------
// mode 0: s-GEMM  grid (4, 72)   out g_spart[by]   (8 kb16 per split)
// mode 1: G-GEMM  grid (72, 4)   out g_Gpart[by]   (8 bb16 per split)
// CTA: 4 warps, each 32m x 160n.
__global__ void __launch_bounds__(128) mma_gemm_kernel(int mode) {
    const int t = threadIdx.x, w = t >> 5, l = t & 31;
    const int gid = l >> 2, tid = l & 3;

    const uint4 *A, *B;
    int AKB;
    float* out;
    if (mode == 0) {
        A = g_afs; B = g_bf; AKB = KB16_S;
        out = &g_spart[blockIdx.y][0];
    } else {
        A = g_afg; B = g_vf; AKB = KB16_G;
        out = &g_Gpart[blockIdx.y][0];
    }
    const int mtbase = blockIdx.x * 8 + w * 2;
    const int kb0 = blockIdx.y * 8;

    float d[2][NT_N][4];
    #pragma unroll
    for (int a = 0; a < 2; a++)
        #pragma unroll
        for (int nt = 0; nt < NT_N; nt++)
            #pragma unroll
            for (int e = 0; e < 4; e++) d[a][nt][e] = 0.0f;

    #pragma unroll 1
    for (int kb = 0; kb < 8; ++kb) {
        size_t a0base = (((size_t)(mtbase + 0) * AKB + kb0 + kb) * 2) * 32 + l;
        size_t a1base = (((size_t)(mtbase + 1) * AKB + kb0 + kb) * 2) * 32 + l;
        uint4 a0h = A[a0base],      a0l = A[a0base + 32];
        uint4 a1h = A[a1base],      a1l = A[a1base + 32];
        const uint4* Bk = &B[(size_t)(kb0 + kb) * NT_N * 32 + l];
        #pragma unroll
        for (int nt = 0; nt < NT_N; nt++) {
            uint4 b = Bk[nt * 32];
            // D += Ah*Bh + Ah*Bl + Al*Bh
            mma_bf16(d[0][nt], a0h.x, a0h.y, a0h.z, a0h.w, b.x, b.y);
            mma_bf16(d[0][nt], a0h.x, a0h.y, a0h.z, a0h.w, b.z, b.w);
            mma_bf16(d[0][nt], a0l.x, a0l.y, a0l.z, a0l.w, b.x, b.y);
            mma_bf16(d[1][nt], a1h.x, a1h.y, a1h.z, a1h.w, b.x, b.y);
            mma_bf16(d[1][nt], a1h.x, a1h.y, a1h.z, a1h.w, b.z, b.w);
            mma_bf16(d[1][nt], a1l.x, a1l.y, a1l.z, a1l.w, b.x, b.y);
        }
    }

    #pragma unroll
    for (int a = 0; a < 2; a++) {
        int m = (mtbase + a) * 16 + gid;
        #pragma unroll
        for (int nt = 0; nt < NT_N; nt++) {
            int col = nt * 8 + tid * 2;
            *(float2*)&out[(size_t)m * N_TOT + col] = make_float2(d[a][nt][0], d[a][nt][1]);
            *(float2*)&out[(size_t)(m + 8) * N_TOT + col] = make_float2(d[a][nt][2], d[a][nt][3]);
        }
    }
}

// ---------------- reduce split-K + squash ----------------
__global__ void squash_kernel(float* __restrict__ out, int write_out) {
    int tid = blockIdx.x * 256 + threadIdx.x;   // < 81920
    float sv = 0.0f;
    #pragma unroll 8
    for (int sp = 0; sp < KSPLIT_S; ++sp) sv += g_spart[sp][tid];
    float sq = sv * sv;
    #pragma unroll
    for (int off = 8; off; off >>= 1) sq += __shfl_xor_sync(~0u, sq, off);
    float norm = sqrtf(sq + 1e-8f);
    float vv = (sq / (1.0f + sq)) * (sv / norm);
    g_v[tid] = vv;
    if (write_out) out[tid] = vv;
}

// ---------------- b[i,o] += (1/512) * sum over 8x16 block of Wt .* (sum Gpart) ----------------
__global__ void b_update_kernel() {
    int w = (blockIdx.x * 256 + threadIdx.x) >> 5;
    int lane = threadIdx.x & 31;
    if (w >= I_CAPS * O_CAPS) return;
    int i = w / O_CAPS, o = w - i * O_CAPS;
    int row = i * 8 + (lane >> 2);
    int col = o * 16 + (lane & 3) * 4;
    int base = row * N_TOT + col;
    float4 wv = *(const float4*)&g_Wt[base];
    float4 g0 = *(const float4*)&g_Gpart[0][base];
    float4 g1 = *(const float4*)&g_Gpart[1][base];
    float4 g2 = *(const float4*)&g_Gpart[2][base];
    float4 g3 = *(const float4*)&g_Gpart[3][base];
    float dd = wv.x * (g0.x + g1.x + g2.x + g3.x)
             + wv.y * (g0.y + g1.y + g2.y + g3.y)
             + wv.z * (g0.z + g1.z + g2.z + g3.z)
             + wv.w * (g0.w + g1.w + g2.w + g3.w);
    #pragma unroll
    for (int off = 16; off; off >>= 1) dd += __shfl_xor_sync(~0u, dd, off);
    if (lane == 0) g_b[w] += dd * (1.0f / (float)B_SZ);
}

// ---------------- launch ----------------
extern "C" void kernel_launch(void* const* d_in, const int* in_sizes, int n_in,
                              void* d_out, int out_size) {
    const float* x = (const float*)d_in[0];
    const float* W = (const float*)d_in[1];
    if (n_in >= 2 && in_sizes[0] == I_CAPS * O_CAPS * P_SZ * Q_SZ) {
        W = (const float*)d_in[0];
        x = (const float*)d_in[1];
    }
    float* out = (float*)d_out;

    wt_kernel<<<(K_TOT * N_TOT + 255) / 256, 256>>>(W);
    xprep_kernel<<<dim3(K_TOT / 128, B_SZ / 16), 256>>>(x);

    for (int it = 0; it < 3; ++it) {
        softmax_kernel<<<1, 32 * O_CAPS>>>();
        bfrag_kernel<<<(KB16_S * NT_N) / 8, 256>>>(W);
        mma_gemm_kernel<<<dim3(MT_S / 8, KSPLIT_S), 128>>>(0);
        squash_kernel<<<(B_SZ * N_TOT) / 256, 256>>>(out, it == 2 ? 1 : 0);
        if (it < 2) {
            vfrag_kernel<<<(KB16_G * NT_N) / 8, 256>>>();
            mma_gemm_kernel<<<dim3(MT_G / 8, BSPLIT_G), 128>>>(1);
            b_update_kernel<<<(I_CAPS * O_CAPS * 32 + 255) / 256, 256>>>();
        }
    }
}